// round 13
// baseline (speedup 1.0000x reference)
#include <cuda_runtime.h>
#include <cuda_fp16.h>
#include <cstdint>
#include <cstddef>

#define NROWS 8192
#define DIMX  1024
#define HIDN  2048
#define H2    4096
#define QK    200
#define QKP   256

// scratch
__device__ __half g_xs  [(size_t)NROWS * DIMX];        // x fp16 single
__device__ __half g_WhT [(size_t)H2    * DIMX];        // W_hidden^T fp16 single
__device__ __half g_WqkT[(size_t)QKP   * 2 * DIMX];    // W_qk^T split hi|lo
__device__ __half g_WoT [(size_t)DIMX  * HIDN];        // W_out^T fp16 single
__device__ float  g_hid [(size_t)NROWS * H2];          // silu(x@Wh+b) f32 [v|gate]
__device__ __half g_vT  [(size_t)HIDN  * NROWS];       // v^T fp16 single
__device__ __half g_q   [(size_t)NROWS * QKP];         // q fp16 single
__device__ __half g_k   [(size_t)NROWS * QKP];         // k fp16 single
__device__ __half g_attn[(size_t)NROWS * NROWS];       // relu(sim)^2 * 1024 fp16
__device__ __half g_o   [(size_t)NROWS * HIDN];        // (attn@v)/1024*gate fp16

__device__ __forceinline__ uint32_t s2u(const void* p) {
    uint32_t r;
    asm("{ .reg .u64 t; cvta.to.shared.u64 t, %1; cvt.u32.u64 %0, t; }" : "=r"(r) : "l"(p));
    return r;
}
__device__ __forceinline__ uint32_t sw(uint32_t b) { return b ^ ((b >> 3) & 0x70); }
__device__ __forceinline__ void ldm4(uint32_t* r, uint32_t addr) {
    asm volatile("ldmatrix.sync.aligned.m8n8.x4.shared.b16 {%0,%1,%2,%3}, [%4];"
                 : "=r"(r[0]), "=r"(r[1]), "=r"(r[2]), "=r"(r[3]) : "r"(addr));
}
__device__ __forceinline__ void mma16816h(float* c, const uint32_t* a, const uint32_t* b) {
    asm volatile("mma.sync.aligned.m16n8k16.row.col.f32.f16.f16.f32 "
                 "{%0,%1,%2,%3}, {%4,%5,%6,%7}, {%8,%9}, {%0,%1,%2,%3};"
                 : "+f"(c[0]), "+f"(c[1]), "+f"(c[2]), "+f"(c[3])
                 : "r"(a[0]), "r"(a[1]), "r"(a[2]), "r"(a[3]), "r"(b[0]), "r"(b[1]));
}
__device__ __forceinline__ void hsplit(float v, __half& h, __half& l) {
    h = __float2half(v);
    l = __float2half(v - __half2float(h));
}

// ============ unified fp16 GEMM, tile 128x128 (warp tile 64x32) ============
// A[M,K] single fp16 x B[N,BT*K]^T (BT=1 single, BT=2 hi|lo 2-term), fp32 accum.
// EPI 0: acc*(1/1024)*e0[row*ld_e0+col] -> fp16            (gate multiply)
// EPI 1: (acc+e0[col])*e1[row*DIMX+col] -> f32             (bias + residual mult)
// EPI 2: silu(acc+e0[col]) -> f32                           (hidden)
// EPI 3: relu(acc*0.03125)^2*1024 -> fp16                   (attention scores)
// EPI 4: s=silu(acc+e0[col]); q=s*e1[col]+e2[col], k=s*e1[QK+col]+e2[QK+col]
//        -> fp16 to Cv and Cv2; cols>=QK forced to 0        (fused qk affine)
template <int BT, int EPI>
__global__ void __launch_bounds__(256, 2)
gemm_h(int K, const __half* __restrict__ A, const __half* __restrict__ B,
       void* __restrict__ Cv, int ldc,
       const float* __restrict__ e0, int ld_e0, const float* __restrict__ e1,
       void* __restrict__ Cv2, const float* __restrict__ e2) {
    constexpr int NST = (BT == 1) ? 3 : 2;
    constexpr int STG = (1 + BT) * 16384;
    extern __shared__ char smem_raw[];
    const uint32_t sbase = (s2u(smem_raw) + 1023u) & ~1023u;
    const int tid = threadIdx.x, lane = tid & 31, wid = tid >> 5;
    const int wm = wid & 1, wn = wid >> 1;
    const int bm = blockIdx.y * 128, bn = blockIdx.x * 128;
    const size_t ldb = (size_t)BT * K;
    const int nch = K / 64;

    auto load_chunk = [&](int c, int stg) {
        const size_t kcol = (size_t)c * 64;
        const uint32_t sA = sbase + stg * STG, sBh = sA + 16384, sBl = sA + 32768;
#pragma unroll
        for (int i = 0; i < 4; i++) {
            int idx = tid + i * 256, row = idx >> 3, seg = idx & 7;
            uint32_t b = sw((uint32_t)(row << 7) + (uint32_t)(seg << 4));
            asm volatile("cp.async.cg.shared.global [%0], [%1], 16;"
                         :: "r"(sA + b), "l"(A + (size_t)(bm + row) * K + kcol + seg * 8));
        }
#pragma unroll
        for (int i = 0; i < 4; i++) {
            int idx = tid + i * 256, row = idx >> 3, seg = idx & 7;
            uint32_t b = sw((uint32_t)(row << 7) + (uint32_t)(seg << 4));
            const __half* src = B + (size_t)(bn + row) * ldb + kcol + seg * 8;
            asm volatile("cp.async.cg.shared.global [%0], [%1], 16;" :: "r"(sBh + b), "l"(src));
            if constexpr (BT == 2)
                asm volatile("cp.async.cg.shared.global [%0], [%1], 16;" :: "r"(sBl + b), "l"(src + K));
        }
        asm volatile("cp.async.commit_group;");
    };

    float acc[4][4][4];
#pragma unroll
    for (int t = 0; t < 4; t++)
#pragma unroll
        for (int u = 0; u < 4; u++)
#pragma unroll
            for (int v = 0; v < 4; v++) acc[t][u][v] = 0.0f;

#pragma unroll
    for (int p = 0; p < NST - 1; p++) load_chunk(p, p);

    const int a_row = wm * 64 + (lane & 15);
    const int a_kx  = (lane >> 4) << 3;
    const int b_row = wn * 32 + (lane & 7) + ((lane >> 4) << 3);
    const int b_kx  = ((lane >> 3) & 1) << 3;

    int st = 0;
    for (int c = 0; c < nch; c++) {
        asm volatile("cp.async.wait_group %0;" :: "n"(NST - 2));
        __syncthreads();
        if (c + NST - 1 < nch) load_chunk(c + NST - 1, (c + NST - 1) % NST);
        else asm volatile("cp.async.commit_group;");

        const uint32_t sA = sbase + st * STG, sBh = sA + 16384, sBl = sA + 32768;
#pragma unroll
        for (int s = 0; s < 4; s++) {
            uint32_t Af[4][4], Bhf[2][4], Blf[2][4];
#pragma unroll
            for (int t = 0; t < 4; t++) {
                uint32_t rb = (uint32_t)(a_row + t * 16) << 7;
                ldm4(Af[t], sA + sw(rb + (uint32_t)((s * 16 + a_kx) << 1)));
            }
#pragma unroll
            for (int p = 0; p < 2; p++) {
                uint32_t rb = (uint32_t)(b_row + p * 16) << 7;
                int kc = s * 16 + b_kx;
                ldm4(Bhf[p], sBh + sw(rb + (uint32_t)(kc << 1)));
                if constexpr (BT == 2) ldm4(Blf[p], sBl + sw(rb + (uint32_t)(kc << 1)));
            }
#pragma unroll
            for (int t = 0; t < 4; t++)
#pragma unroll
                for (int u = 0; u < 4; u++) {
                    mma16816h(acc[t][u], Af[t], &Bhf[u >> 1][(u & 1) * 2]);
                    if constexpr (BT == 2) mma16816h(acc[t][u], Af[t], &Blf[u >> 1][(u & 1) * 2]);
                }
        }
        st = (st + 1) % NST;
    }

#pragma unroll
    for (int t = 0; t < 4; t++) {
        int row0 = bm + wm * 64 + t * 16 + (lane >> 2);
#pragma unroll
        for (int u = 0; u < 4; u++) {
            int col = bn + wn * 32 + u * 8 + (lane & 3) * 2;
#pragma unroll
            for (int h = 0; h < 2; h++) {
                int row = row0 + h * 8;
                float v0 = acc[t][u][h * 2], v1 = acc[t][u][h * 2 + 1];
                if constexpr (EPI == 0) {
                    const float* gr = e0 + (size_t)row * ld_e0 + col;
                    *(__half2*)((__half*)Cv + (size_t)row * ldc + col) =
                        __floats2half2_rn(v0 * 9.765625e-4f * gr[0], v1 * 9.765625e-4f * gr[1]);
                } else if constexpr (EPI == 1) {
                    float t0 = v0 + e0[col], t1 = v1 + e0[col + 1];
                    const float* xr = e1 + (size_t)row * DIMX + col;
                    *(float2*)((float*)Cv + (size_t)row * ldc + col) =
                        make_float2(t0 * xr[0], t1 * xr[1]);
                } else if constexpr (EPI == 2) {
                    float t0 = v0 + e0[col], t1 = v1 + e0[col + 1];
                    *(float2*)((float*)Cv + (size_t)row * ldc + col) =
                        make_float2(t0 / (1.0f + __expf(-t0)), t1 / (1.0f + __expf(-t1)));
                } else if constexpr (EPI == 3) {
                    float s0 = fmaxf(v0 * 0.03125f, 0.0f), s1 = fmaxf(v1 * 0.03125f, 0.0f);
                    *(__half2*)((__half*)Cv + (size_t)row * ldc + col) =
                        __floats2half2_rn(s0 * s0 * 1024.0f, s1 * s1 * 1024.0f);
                } else {
                    float qv[2], kv[2];
#pragma unroll
                    for (int z = 0; z < 2; z++) {
                        int cz = col + z;
                        float vz = (z == 0) ? v0 : v1;
                        if (cz < QK) {
                            float tt = vz + e0[cz];
                            float ss = tt / (1.0f + __expf(-tt));
                            qv[z] = ss * e1[cz]      + e2[cz];
                            kv[z] = ss * e1[QK + cz] + e2[QK + cz];
                        } else { qv[z] = 0.0f; kv[z] = 0.0f; }
                    }
                    *(__half2*)((__half*)Cv  + (size_t)row * ldc + col) = __floats2half2_rn(qv[0], qv[1]);
                    *(__half2*)((__half*)Cv2 + (size_t)row * ldc + col) = __floats2half2_rn(kv[0], kv[1]);
                }
            }
        }
    }
}

// ============ big-tile fp16 GEMM, tile 128x256 (warp tile 64x64) ============
// A[M,K] x B[N,K]^T single fp16, 1 CTA/SM, 3-stage. EPI 0 only (gate multiply).
constexpr int BSTG = 49152;                       // A 16KB + B 32KB
constexpr int SMEM_BIG = 1024 + 3 * BSTG;         // 148480
__global__ void __launch_bounds__(256, 1)
gemm_big(int K, const __half* __restrict__ A, const __half* __restrict__ B,
         __half* __restrict__ C, int ldc, const float* __restrict__ e0, int ld_e0) {
    extern __shared__ char smem_raw[];
    const uint32_t sbase = (s2u(smem_raw) + 1023u) & ~1023u;
    const int tid = threadIdx.x, lane = tid & 31, wid = tid >> 5;
    const int wm = wid & 1, wn = wid >> 1;              // 2 x 4 warp grid
    const int bm = blockIdx.y * 128, bn = blockIdx.x * 256;
    const int nch = K / 64;

    auto load_chunk = [&](int c, int stg) {
        const size_t kcol = (size_t)c * 64;
        const uint32_t sA = sbase + stg * BSTG, sB = sA + 16384;
#pragma unroll
        for (int i = 0; i < 4; i++) {
            int idx = tid + i * 256, row = idx >> 3, seg = idx & 7;
            uint32_t b = sw((uint32_t)(row << 7) + (uint32_t)(seg << 4));
            asm volatile("cp.async.cg.shared.global [%0], [%1], 16;"
                         :: "r"(sA + b), "l"(A + (size_t)(bm + row) * K + kcol + seg * 8));
        }
#pragma unroll
        for (int i = 0; i < 8; i++) {
            int idx = tid + i * 256, row = idx >> 3, seg = idx & 7;
            uint32_t b = sw((uint32_t)(row << 7) + (uint32_t)(seg << 4));
            asm volatile("cp.async.cg.shared.global [%0], [%1], 16;"
                         :: "r"(sB + b), "l"(B + (size_t)(bn + row) * K + kcol + seg * 8));
        }
        asm volatile("cp.async.commit_group;");
    };

    float acc[4][8][4];
#pragma unroll
    for (int t = 0; t < 4; t++)
#pragma unroll
        for (int u = 0; u < 8; u++)
#pragma unroll
            for (int v = 0; v < 4; v++) acc[t][u][v] = 0.0f;

    load_chunk(0, 0); load_chunk(1, 1);

    const int a_row = wm * 64 + (lane & 15);
    const int a_kx  = (lane >> 4) << 3;
    const int b_row = wn * 64 + (lane & 7) + ((lane >> 4) << 3);
    const int b_kx  = ((lane >> 3) & 1) << 3;

    int st = 0;
    for (int c = 0; c < nch; c++) {
        asm volatile("cp.async.wait_group 1;");
        __syncthreads();
        if (c + 2 < nch) load_chunk(c + 2, (c + 2) % 3);
        else asm volatile("cp.async.commit_group;");

        const uint32_t sA = sbase + st * BSTG, sB = sA + 16384;
#pragma unroll
        for (int s = 0; s < 4; s++) {
            uint32_t Af[4][4], Bf[4][4];
#pragma unroll
            for (int t = 0; t < 4; t++) {
                uint32_t rb = (uint32_t)(a_row + t * 16) << 7;
                ldm4(Af[t], sA + sw(rb + (uint32_t)((s * 16 + a_kx) << 1)));
            }
#pragma unroll
            for (int p = 0; p < 4; p++) {
                uint32_t rb = (uint32_t)(b_row + p * 16) << 7;
                ldm4(Bf[p], sB + sw(rb + (uint32_t)((s * 16 + b_kx) << 1)));
            }
#pragma unroll
            for (int t = 0; t < 4; t++)
#pragma unroll
                for (int u = 0; u < 8; u++)
                    mma16816h(acc[t][u], Af[t], &Bf[u >> 1][(u & 1) * 2]);
        }
        st = (st + 1) % 3;
    }

#pragma unroll
    for (int t = 0; t < 4; t++) {
        int row0 = bm + wm * 64 + t * 16 + (lane >> 2);
#pragma unroll
        for (int u = 0; u < 8; u++) {
            int col = bn + wn * 64 + u * 8 + (lane & 3) * 2;
#pragma unroll
            for (int h = 0; h < 2; h++) {
                int row = row0 + h * 8;
                const float* gr = e0 + (size_t)row * ld_e0 + col;
                *(__half2*)(C + (size_t)row * ldc + col) =
                    __floats2half2_rn(acc[t][u][h * 2]     * 9.765625e-4f * gr[0],
                                      acc[t][u][h * 2 + 1] * 9.765625e-4f * gr[1]);
            }
        }
    }
}

// fp32 -> fp16 single cast
__global__ void cast_f16(const float* __restrict__ in, __half* __restrict__ out, int total) {
    int i = blockIdx.x * blockDim.x + threadIdx.x;
    if (i < total) out[i] = __float2half(in[i]);
}

// fp32 [Kd,Nd](ld=ldi) -> fp16 [Npad, 2Kd] transposed+split
__global__ void transpose_split_f16(const float* __restrict__ in, int ldi, int Kd, int Nd,
                                    __half* __restrict__ out) {
    __shared__ float t[32][33];
    int c = blockIdx.x * 32 + threadIdx.x, r = blockIdx.y * 32 + threadIdx.y;
    t[threadIdx.y][threadIdx.x] = (c < Nd) ? in[(size_t)r * ldi + c] : 0.0f;
    __syncthreads();
    int n = blockIdx.x * 32 + threadIdx.y, k = blockIdx.y * 32 + threadIdx.x;
    __half h, l;
    hsplit(t[threadIdx.x][threadIdx.y], h, l);
    out[(size_t)n * 2 * Kd + k] = h;
    out[(size_t)n * 2 * Kd + Kd + k] = l;
}

// fp32 -> fp16 single transposed [Nd, Kd]
__global__ void transpose_f16(const float* __restrict__ in, int ldi, int Kd, int Nd,
                              __half* __restrict__ out) {
    __shared__ float t[32][33];
    int c = blockIdx.x * 32 + threadIdx.x, r = blockIdx.y * 32 + threadIdx.y;
    t[threadIdx.y][threadIdx.x] = (c < Nd) ? in[(size_t)r * ldi + c] : 0.0f;
    __syncthreads();
    int n = blockIdx.x * 32 + threadIdx.y, k = blockIdx.y * 32 + threadIdx.x;
    out[(size_t)n * Kd + k] = __float2half(t[threadIdx.x][threadIdx.y]);
}

static inline int cdiv(int a, int b) { return (a + b - 1) / b; }
constexpr int SMEM_H = 1024 + 2 * 3 * 16384;   // 99328

extern "C" void kernel_launch(void* const* d_in, const int* in_sizes, int n_in,
                              void* d_out, int out_size) {
    const float* x        = (const float*)d_in[0];
    const float* W_hidden = (const float*)d_in[1];
    const float* b_hidden = (const float*)d_in[2];
    const float* W_qk     = (const float*)d_in[3];
    const float* b_qk     = (const float*)d_in[4];
    const float* gamma    = (const float*)d_in[5];
    const float* beta     = (const float*)d_in[6];
    const float* W_out    = (const float*)d_in[7];
    const float* b_out    = (const float*)d_in[8];
    float* out = (float*)d_out;

    __half *xs, *WhT, *WqkT, *WoT, *vT, *q, *k, *attn, *o;
    float *hid;
    cudaGetSymbolAddress((void**)&xs, g_xs);     cudaGetSymbolAddress((void**)&WhT, g_WhT);
    cudaGetSymbolAddress((void**)&WqkT, g_WqkT); cudaGetSymbolAddress((void**)&WoT, g_WoT);
    cudaGetSymbolAddress((void**)&vT, g_vT);     cudaGetSymbolAddress((void**)&q, g_q);
    cudaGetSymbolAddress((void**)&k, g_k);       cudaGetSymbolAddress((void**)&attn, g_attn);
    cudaGetSymbolAddress((void**)&o, g_o);       cudaGetSymbolAddress((void**)&hid, g_hid);

    cudaFuncSetAttribute((void*)gemm_h<1, 2>, cudaFuncAttributeMaxDynamicSharedMemorySize, SMEM_H);
    cudaFuncSetAttribute((void*)gemm_h<2, 4>, cudaFuncAttributeMaxDynamicSharedMemorySize, SMEM_H);
    cudaFuncSetAttribute((void*)gemm_h<1, 3>, cudaFuncAttributeMaxDynamicSharedMemorySize, SMEM_H);
    cudaFuncSetAttribute((void*)gemm_h<1, 1>, cudaFuncAttributeMaxDynamicSharedMemorySize, SMEM_H);
    cudaFuncSetAttribute((void*)gemm_big,     cudaFuncAttributeMaxDynamicSharedMemorySize, SMEM_BIG);

    // Fork-join (leaked per call by design; only correctness+capture execute host code)
    cudaStream_t s2;
    cudaStreamCreate(&s2);
    cudaEvent_t ev0, ev2;
    cudaEventCreate(&ev0);
    cudaEventCreate(&ev2);

    transpose_f16<<<dim3(DIMX / 32, HIDN / 32), dim3(32, 32), 0, s2>>>(W_out, DIMX, HIDN, DIMX, WoT);
    transpose_split_f16<<<dim3(QKP / 32, DIMX / 32), dim3(32, 32), 0, s2>>>(W_qk, QK, DIMX, QK, WqkT);

    cast_f16<<<cdiv(NROWS * DIMX, 256), 256>>>(x, xs, NROWS * DIMX);
    transpose_f16<<<dim3(H2 / 32, DIMX / 32), dim3(32, 32)>>>(W_hidden, H2, DIMX, H2, WhT);
    cudaEventRecord(ev0, 0);
    cudaStreamWaitEvent(s2, ev0, 0);

    // s2: G2 (q,k) -> G3 (attn)
    gemm_h<2, 4><<<dim3(QKP / 128, NROWS / 128), 256, SMEM_H, s2>>>(
        DIMX, xs, WqkT, q, QKP, b_qk, 0, gamma, k, beta);
    gemm_h<1, 3><<<dim3(NROWS / 128, NROWS / 128), 256, SMEM_H, s2>>>(
        QKP, q, k, attn, NROWS, nullptr, 0, nullptr, nullptr, nullptr);
    cudaEventRecord(ev2, s2);

    // stream 0: G1 (hid) -> vT
    gemm_h<1, 2><<<dim3(H2 / 128, NROWS / 128), 256, SMEM_H>>>(
        DIMX, xs, WhT, hid, H2, b_hidden, 0, nullptr, nullptr, nullptr);
    transpose_f16<<<dim3(HIDN / 32, NROWS / 32), dim3(32, 32)>>>(hid, H2, NROWS, HIDN, vT);

    // join; G4 big-tile: o = (attn @ v)/1024 * gate -> fp16 [8192,2048]
    cudaStreamWaitEvent(0, ev2, 0);
    gemm_big<<<dim3(HIDN / 256, NROWS / 128), 256, SMEM_BIG>>>(
        NROWS, attn, vT, o, HIDN, hid + HIDN, H2);
    // G5: out = (o @ W_out + b) * x -> f32 [8192,1024]
    gemm_h<1, 1><<<dim3(DIMX / 128, NROWS / 128), 256, SMEM_H>>>(
        HIDN, o, WoT, out, DIMX, b_out, 0, x, nullptr, nullptr);
}

// round 14
// speedup vs baseline: 1.0660x; 1.0660x over previous
#include <cuda_runtime.h>
#include <cuda_fp16.h>
#include <cstdint>
#include <cstddef>

#define NROWS 8192
#define DIMX  1024
#define HIDN  2048
#define H2    4096
#define QK    200
#define QKP   256

// scratch
__device__ __half g_xs  [(size_t)NROWS * DIMX];        // x fp16
__device__ __half g_WhT [(size_t)H2    * DIMX];        // W_hidden^T fp16
__device__ __half g_WqkT[(size_t)QKP   * 2 * DIMX];    // W_qk^T split hi|lo
__device__ __half g_WoT [(size_t)DIMX  * HIDN];        // W_out^T fp16
__device__ __half g_v   [(size_t)NROWS * HIDN];        // silu v fp16
__device__ __half g_gate[(size_t)NROWS * HIDN];        // silu gate fp16
__device__ __half g_vT  [(size_t)HIDN  * NROWS];       // v^T fp16
__device__ __half g_q   [(size_t)NROWS * QKP];         // q fp16
__device__ __half g_k   [(size_t)NROWS * QKP];         // k fp16
__device__ __half g_attn[(size_t)NROWS * NROWS];       // relu(sim)^2 * 1024 fp16
__device__ __half g_o   [(size_t)NROWS * HIDN];        // (attn@v)/1024*gate fp16

__device__ __forceinline__ uint32_t s2u(const void* p) {
    uint32_t r;
    asm("{ .reg .u64 t; cvta.to.shared.u64 t, %1; cvt.u32.u64 %0, t; }" : "=r"(r) : "l"(p));
    return r;
}
__device__ __forceinline__ uint32_t sw(uint32_t b) { return b ^ ((b >> 3) & 0x70); }
__device__ __forceinline__ void ldm4(uint32_t* r, uint32_t addr) {
    asm volatile("ldmatrix.sync.aligned.m8n8.x4.shared.b16 {%0,%1,%2,%3}, [%4];"
                 : "=r"(r[0]), "=r"(r[1]), "=r"(r[2]), "=r"(r[3]) : "r"(addr));
}
__device__ __forceinline__ void mma16816h(float* c, const uint32_t* a, const uint32_t* b) {
    asm volatile("mma.sync.aligned.m16n8k16.row.col.f32.f16.f16.f32 "
                 "{%0,%1,%2,%3}, {%4,%5,%6,%7}, {%8,%9}, {%0,%1,%2,%3};"
                 : "+f"(c[0]), "+f"(c[1]), "+f"(c[2]), "+f"(c[3])
                 : "r"(a[0]), "r"(a[1]), "r"(a[2]), "r"(a[3]), "r"(b[0]), "r"(b[1]));
}
__device__ __forceinline__ void hsplit(float v, __half& h, __half& l) {
    h = __float2half(v);
    l = __float2half(v - __half2float(h));
}

// ============ unified fp16 GEMM, tile 128x128 (warp tile 64x32), 2 CTA/SM ====
// A[M,K] single fp16 x B[N,BT*K]^T (BT=1 single, BT=2 hi|lo 2-term), fp32 accum.
// moff: M-offset in tiles (row-split launches).
// EPI 0: acc*(1/1024)*eh[row*ld_e0+col] -> fp16 (gate fp16)       (G4)
// EPI 1: (acc+e0[col])*e1[row*DIMX+col] -> f32                     (G5)
// EPI 3: relu(acc*0.03125)^2*1024 -> fp16                          (G3)
// EPI 4: s=silu(acc+e0[col]); q=s*e1[c]+e2[c], k=s*e1[QK+c]+e2[QK+c] -> Cv,Cv2 (G2)
// EPI 5: s=silu(acc+e0[col]); col<HIDN -> v (Cv), else gate (Cv2), fp16 (G1)
template <int BT, int EPI>
__global__ void __launch_bounds__(256, 2)
gemm_h(int K, const __half* __restrict__ A, const __half* __restrict__ B,
       void* __restrict__ Cv, int ldc,
       const float* __restrict__ e0, int ld_e0, const float* __restrict__ e1,
       void* __restrict__ Cv2, const float* __restrict__ e2,
       const __half* __restrict__ eh, int moff) {
    constexpr int NST = (BT == 1) ? 3 : 2;
    constexpr int STG = (1 + BT) * 16384;
    extern __shared__ char smem_raw[];
    const uint32_t sbase = (s2u(smem_raw) + 1023u) & ~1023u;
    const int tid = threadIdx.x, lane = tid & 31, wid = tid >> 5;
    const int wm = wid & 1, wn = wid >> 1;
    const int bm = (blockIdx.y + moff) * 128, bn = blockIdx.x * 128;
    const size_t ldb = (size_t)BT * K;
    const int nch = K / 64;

    auto load_chunk = [&](int c, int stg) {
        const size_t kcol = (size_t)c * 64;
        const uint32_t sA = sbase + stg * STG, sBh = sA + 16384, sBl = sA + 32768;
#pragma unroll
        for (int i = 0; i < 4; i++) {
            int idx = tid + i * 256, row = idx >> 3, seg = idx & 7;
            uint32_t b = sw((uint32_t)(row << 7) + (uint32_t)(seg << 4));
            asm volatile("cp.async.cg.shared.global [%0], [%1], 16;"
                         :: "r"(sA + b), "l"(A + (size_t)(bm + row) * K + kcol + seg * 8));
        }
#pragma unroll
        for (int i = 0; i < 4; i++) {
            int idx = tid + i * 256, row = idx >> 3, seg = idx & 7;
            uint32_t b = sw((uint32_t)(row << 7) + (uint32_t)(seg << 4));
            const __half* src = B + (size_t)(bn + row) * ldb + kcol + seg * 8;
            asm volatile("cp.async.cg.shared.global [%0], [%1], 16;" :: "r"(sBh + b), "l"(src));
            if constexpr (BT == 2)
                asm volatile("cp.async.cg.shared.global [%0], [%1], 16;" :: "r"(sBl + b), "l"(src + K));
        }
        asm volatile("cp.async.commit_group;");
    };

    float acc[4][4][4];
#pragma unroll
    for (int t = 0; t < 4; t++)
#pragma unroll
        for (int u = 0; u < 4; u++)
#pragma unroll
            for (int v = 0; v < 4; v++) acc[t][u][v] = 0.0f;

#pragma unroll
    for (int p = 0; p < NST - 1; p++) load_chunk(p, p);

    const int a_row = wm * 64 + (lane & 15);
    const int a_kx  = (lane >> 4) << 3;
    const int b_row = wn * 32 + (lane & 7) + ((lane >> 4) << 3);
    const int b_kx  = ((lane >> 3) & 1) << 3;

    int st = 0;
    for (int c = 0; c < nch; c++) {
        asm volatile("cp.async.wait_group %0;" :: "n"(NST - 2));
        __syncthreads();
        if (c + NST - 1 < nch) load_chunk(c + NST - 1, (c + NST - 1) % NST);
        else asm volatile("cp.async.commit_group;");

        const uint32_t sA = sbase + st * STG, sBh = sA + 16384, sBl = sA + 32768;
#pragma unroll
        for (int s = 0; s < 4; s++) {
            uint32_t Af[4][4], Bhf[2][4], Blf[2][4];
#pragma unroll
            for (int t = 0; t < 4; t++) {
                uint32_t rb = (uint32_t)(a_row + t * 16) << 7;
                ldm4(Af[t], sA + sw(rb + (uint32_t)((s * 16 + a_kx) << 1)));
            }
#pragma unroll
            for (int p = 0; p < 2; p++) {
                uint32_t rb = (uint32_t)(b_row + p * 16) << 7;
                int kc = s * 16 + b_kx;
                ldm4(Bhf[p], sBh + sw(rb + (uint32_t)(kc << 1)));
                if constexpr (BT == 2) ldm4(Blf[p], sBl + sw(rb + (uint32_t)(kc << 1)));
            }
#pragma unroll
            for (int t = 0; t < 4; t++)
#pragma unroll
                for (int u = 0; u < 4; u++) {
                    mma16816h(acc[t][u], Af[t], &Bhf[u >> 1][(u & 1) * 2]);
                    if constexpr (BT == 2) mma16816h(acc[t][u], Af[t], &Blf[u >> 1][(u & 1) * 2]);
                }
        }
        st = (st + 1) % NST;
    }

#pragma unroll
    for (int t = 0; t < 4; t++) {
        int row0 = bm + wm * 64 + t * 16 + (lane >> 2);
#pragma unroll
        for (int u = 0; u < 4; u++) {
            int col = bn + wn * 32 + u * 8 + (lane & 3) * 2;
#pragma unroll
            for (int h = 0; h < 2; h++) {
                int row = row0 + h * 8;
                float v0 = acc[t][u][h * 2], v1 = acc[t][u][h * 2 + 1];
                if constexpr (EPI == 0) {
                    __half2 g2 = *(const __half2*)(eh + (size_t)row * ld_e0 + col);
                    *(__half2*)((__half*)Cv + (size_t)row * ldc + col) =
                        __floats2half2_rn(v0 * 9.765625e-4f * __half2float(g2.x),
                                          v1 * 9.765625e-4f * __half2float(g2.y));
                } else if constexpr (EPI == 1) {
                    float t0 = v0 + e0[col], t1 = v1 + e0[col + 1];
                    const float* xr = e1 + (size_t)row * DIMX + col;
                    *(float2*)((float*)Cv + (size_t)row * ldc + col) =
                        make_float2(t0 * xr[0], t1 * xr[1]);
                } else if constexpr (EPI == 3) {
                    float s0 = fmaxf(v0 * 0.03125f, 0.0f), s1 = fmaxf(v1 * 0.03125f, 0.0f);
                    *(__half2*)((__half*)Cv + (size_t)row * ldc + col) =
                        __floats2half2_rn(s0 * s0 * 1024.0f, s1 * s1 * 1024.0f);
                } else if constexpr (EPI == 4) {
                    float qv[2], kv[2];
#pragma unroll
                    for (int z = 0; z < 2; z++) {
                        int cz = col + z;
                        float vz = (z == 0) ? v0 : v1;
                        if (cz < QK) {
                            float tt = vz + e0[cz];
                            float ss = tt / (1.0f + __expf(-tt));
                            qv[z] = ss * e1[cz]      + e2[cz];
                            kv[z] = ss * e1[QK + cz] + e2[QK + cz];
                        } else { qv[z] = 0.0f; kv[z] = 0.0f; }
                    }
                    *(__half2*)((__half*)Cv  + (size_t)row * ldc + col) = __floats2half2_rn(qv[0], qv[1]);
                    *(__half2*)((__half*)Cv2 + (size_t)row * ldc + col) = __floats2half2_rn(kv[0], kv[1]);
                } else {  // EPI == 5: silu -> v (col<HIDN) or gate
                    float t0 = v0 + e0[col], t1 = v1 + e0[col + 1];
                    __half2 hv = __floats2half2_rn(t0 / (1.0f + __expf(-t0)),
                                                   t1 / (1.0f + __expf(-t1)));
                    if (col < HIDN)
                        *(__half2*)((__half*)Cv  + (size_t)row * HIDN + col) = hv;
                    else
                        *(__half2*)((__half*)Cv2 + (size_t)row * HIDN + col - HIDN) = hv;
                }
            }
        }
    }
}

// fp32 -> fp16 single cast
__global__ void cast_f16(const float* __restrict__ in, __half* __restrict__ out, int total) {
    int i = blockIdx.x * blockDim.x + threadIdx.x;
    if (i < total) out[i] = __float2half(in[i]);
}

// fp32 [Kd,Nd](ld=ldi) -> fp16 [Npad, 2Kd] transposed+split
__global__ void transpose_split_f16(const float* __restrict__ in, int ldi, int Kd, int Nd,
                                    __half* __restrict__ out) {
    __shared__ float t[32][33];
    int c = blockIdx.x * 32 + threadIdx.x, r = blockIdx.y * 32 + threadIdx.y;
    t[threadIdx.y][threadIdx.x] = (c < Nd) ? in[(size_t)r * ldi + c] : 0.0f;
    __syncthreads();
    int n = blockIdx.x * 32 + threadIdx.y, k = blockIdx.y * 32 + threadIdx.x;
    __half h, l;
    hsplit(t[threadIdx.x][threadIdx.y], h, l);
    out[(size_t)n * 2 * Kd + k] = h;
    out[(size_t)n * 2 * Kd + Kd + k] = l;
}

// fp32 -> fp16 transposed [Nd, Kd]
__global__ void transpose_f16(const float* __restrict__ in, int ldi, int Kd, int Nd,
                              __half* __restrict__ out) {
    __shared__ float t[32][33];
    int c = blockIdx.x * 32 + threadIdx.x, r = blockIdx.y * 32 + threadIdx.y;
    t[threadIdx.y][threadIdx.x] = (c < Nd) ? in[(size_t)r * ldi + c] : 0.0f;
    __syncthreads();
    int n = blockIdx.x * 32 + threadIdx.y, k = blockIdx.y * 32 + threadIdx.x;
    out[(size_t)n * Kd + k] = __float2half(t[threadIdx.x][threadIdx.y]);
}

// fp16 [Kd,Nd](ld=ldi) -> fp16 transposed [Nd, Kd]
__global__ void transpose_h16(const __half* __restrict__ in, int ldi, int Kd, int Nd,
                              __half* __restrict__ out) {
    __shared__ __half t[32][40];
    int c = blockIdx.x * 32 + threadIdx.x, r = blockIdx.y * 32 + threadIdx.y;
    t[threadIdx.y][threadIdx.x] = in[(size_t)r * ldi + c];
    __syncthreads();
    int n = blockIdx.x * 32 + threadIdx.y, k = blockIdx.y * 32 + threadIdx.x;
    out[(size_t)n * Kd + k] = t[threadIdx.x][threadIdx.y];
}

static inline int cdiv(int a, int b) { return (a + b - 1) / b; }
constexpr int SMEM_H = 1024 + 2 * 3 * 16384;   // 99328

extern "C" void kernel_launch(void* const* d_in, const int* in_sizes, int n_in,
                              void* d_out, int out_size) {
    const float* x        = (const float*)d_in[0];
    const float* W_hidden = (const float*)d_in[1];
    const float* b_hidden = (const float*)d_in[2];
    const float* W_qk     = (const float*)d_in[3];
    const float* b_qk     = (const float*)d_in[4];
    const float* gamma    = (const float*)d_in[5];
    const float* beta     = (const float*)d_in[6];
    const float* W_out    = (const float*)d_in[7];
    const float* b_out    = (const float*)d_in[8];
    float* out = (float*)d_out;

    __half *xs, *WhT, *WqkT, *WoT, *v, *gate, *vT, *q, *k, *attn, *o;
    cudaGetSymbolAddress((void**)&xs, g_xs);     cudaGetSymbolAddress((void**)&WhT, g_WhT);
    cudaGetSymbolAddress((void**)&WqkT, g_WqkT); cudaGetSymbolAddress((void**)&WoT, g_WoT);
    cudaGetSymbolAddress((void**)&v, g_v);       cudaGetSymbolAddress((void**)&gate, g_gate);
    cudaGetSymbolAddress((void**)&vT, g_vT);     cudaGetSymbolAddress((void**)&q, g_q);
    cudaGetSymbolAddress((void**)&k, g_k);       cudaGetSymbolAddress((void**)&attn, g_attn);
    cudaGetSymbolAddress((void**)&o, g_o);

    cudaFuncSetAttribute((void*)gemm_h<1, 5>, cudaFuncAttributeMaxDynamicSharedMemorySize, SMEM_H);
    cudaFuncSetAttribute((void*)gemm_h<2, 4>, cudaFuncAttributeMaxDynamicSharedMemorySize, SMEM_H);
    cudaFuncSetAttribute((void*)gemm_h<1, 3>, cudaFuncAttributeMaxDynamicSharedMemorySize, SMEM_H);
    cudaFuncSetAttribute((void*)gemm_h<1, 0>, cudaFuncAttributeMaxDynamicSharedMemorySize, SMEM_H);
    cudaFuncSetAttribute((void*)gemm_h<1, 1>, cudaFuncAttributeMaxDynamicSharedMemorySize, SMEM_H);

    // Fork-join (objects leaked per call by design; only correctness+capture run host code)
    cudaStream_t s2;
    cudaStreamCreate(&s2);
    cudaEvent_t ev0, ev2, ev4a, ev5a;
    cudaEventCreate(&ev0); cudaEventCreate(&ev2);
    cudaEventCreate(&ev4a); cudaEventCreate(&ev5a);

    // s2: weight transposes off the critical path
    transpose_f16<<<dim3(DIMX / 32, HIDN / 32), dim3(32, 32), 0, s2>>>(W_out, DIMX, HIDN, DIMX, WoT);
    transpose_split_f16<<<dim3(QKP / 32, DIMX / 32), dim3(32, 32), 0, s2>>>(W_qk, QK, DIMX, QK, WqkT);

    // s0: x cast + Wh transpose
    cast_f16<<<cdiv(NROWS * DIMX, 256), 256>>>(x, xs, NROWS * DIMX);
    transpose_f16<<<dim3(H2 / 32, DIMX / 32), dim3(32, 32)>>>(W_hidden, H2, DIMX, H2, WhT);
    cudaEventRecord(ev0, 0);
    cudaStreamWaitEvent(s2, ev0, 0);

    // s2: G2 (q,k fused) -> G3 (attn)
    gemm_h<2, 4><<<dim3(QKP / 128, NROWS / 128), 256, SMEM_H, s2>>>(
        DIMX, xs, WqkT, q, QKP, b_qk, 0, gamma, k, beta, nullptr, 0);
    gemm_h<1, 3><<<dim3(NROWS / 128, NROWS / 128), 256, SMEM_H, s2>>>(
        QKP, q, k, attn, NROWS, nullptr, 0, nullptr, nullptr, nullptr, nullptr, 0);
    cudaEventRecord(ev2, s2);

    // s0: G1 -> v/gate fp16 directly, then vT
    gemm_h<1, 5><<<dim3(H2 / 128, NROWS / 128), 256, SMEM_H>>>(
        DIMX, xs, WhT, v, HIDN, b_hidden, 0, nullptr, gate, nullptr, nullptr, 0);
    transpose_h16<<<dim3(HIDN / 32, NROWS / 32), dim3(32, 32)>>>(v, HIDN, NROWS, HIDN, vT);

    // join attn, then row-split G4 / G5 overlap:
    // G4a (rows 0..4095) -> {G4b (rows 4096..) on s0  ||  G5a (rows 0..4095) on s2} -> G5b
    cudaStreamWaitEvent(0, ev2, 0);
    gemm_h<1, 0><<<dim3(HIDN / 128, NROWS / 256), 256, SMEM_H>>>(
        NROWS, attn, vT, o, HIDN, nullptr, HIDN, nullptr, nullptr, nullptr, gate, 0);
    cudaEventRecord(ev4a, 0);
    gemm_h<1, 0><<<dim3(HIDN / 128, NROWS / 256), 256, SMEM_H>>>(
        NROWS, attn, vT, o, HIDN, nullptr, HIDN, nullptr, nullptr, nullptr, gate, 32);
    cudaStreamWaitEvent(s2, ev4a, 0);
    gemm_h<1, 1><<<dim3(DIMX / 128, NROWS / 256), 256, SMEM_H, s2>>>(
        HIDN, o, WoT, out, DIMX, b_out, 0, x, nullptr, nullptr, nullptr, 0);
    cudaEventRecord(ev5a, s2);
    gemm_h<1, 1><<<dim3(DIMX / 128, NROWS / 256), 256, SMEM_H>>>(
        HIDN, o, WoT, out, DIMX, b_out, 0, x, nullptr, nullptr, nullptr, 32);
    cudaStreamWaitEvent(0, ev5a, 0);
}

// round 15
// speedup vs baseline: 1.1130x; 1.0441x over previous
#include <cuda_runtime.h>
#include <cuda_fp16.h>
#include <cstdint>
#include <cstddef>

#define NROWS 8192
#define DIMX  1024
#define HIDN  2048
#define H2    4096
#define QK    200
#define QKP   256

// scratch
__device__ __half g_xs  [(size_t)NROWS * DIMX];        // x fp16
__device__ __half g_WhT [(size_t)H2    * DIMX];        // W_hidden^T fp16
__device__ __half g_WqkT[(size_t)QKP   * 2 * DIMX];    // W_qk^T split hi|lo
__device__ __half g_WoT [(size_t)DIMX  * HIDN];        // W_out^T fp16
__device__ __half g_v   [(size_t)NROWS * HIDN];        // silu v fp16
__device__ __half g_gate[(size_t)NROWS * HIDN];        // silu gate fp16
__device__ __half g_vT  [(size_t)HIDN  * NROWS];       // v^T fp16
__device__ __half g_q   [(size_t)NROWS * QKP];         // q fp16
__device__ __half g_k   [(size_t)NROWS * QKP];         // k fp16
__device__ __half g_attn[(size_t)NROWS * NROWS];       // relu(sim)^2 * 1024 fp16
__device__ __half g_o   [(size_t)NROWS * HIDN];        // (attn@v)/1024*gate fp16

__device__ __forceinline__ uint32_t s2u(const void* p) {
    uint32_t r;
    asm("{ .reg .u64 t; cvta.to.shared.u64 t, %1; cvt.u32.u64 %0, t; }" : "=r"(r) : "l"(p));
    return r;
}
__device__ __forceinline__ uint32_t sw(uint32_t b) { return b ^ ((b >> 3) & 0x70); }
__device__ __forceinline__ void ldm4(uint32_t* r, uint32_t addr) {
    asm volatile("ldmatrix.sync.aligned.m8n8.x4.shared.b16 {%0,%1,%2,%3}, [%4];"
                 : "=r"(r[0]), "=r"(r[1]), "=r"(r[2]), "=r"(r[3]) : "r"(addr));
}
__device__ __forceinline__ void mma16816h(float* c, const uint32_t* a, const uint32_t* b) {
    asm volatile("mma.sync.aligned.m16n8k16.row.col.f32.f16.f16.f32 "
                 "{%0,%1,%2,%3}, {%4,%5,%6,%7}, {%8,%9}, {%0,%1,%2,%3};"
                 : "+f"(c[0]), "+f"(c[1]), "+f"(c[2]), "+f"(c[3])
                 : "r"(a[0]), "r"(a[1]), "r"(a[2]), "r"(a[3]), "r"(b[0]), "r"(b[1]));
}
__device__ __forceinline__ void hsplit(float v, __half& h, __half& l) {
    h = __float2half(v);
    l = __float2half(v - __half2float(h));
}

// ============ unified fp16 GEMM, tile 128x128 (warp tile 64x32), 2 CTA/SM ====
// A[M,K] single fp16 x B[N,BT*K]^T (BT=1 single, BT=2 hi|lo 2-term), fp32 accum.
// EPI 0: acc*(1/1024)*eh[row*ld_e0+col] -> fp16 (gate fp16)       (G4)
// EPI 1: (acc+e0[col])*e1[row*DIMX+col] -> f32                     (G5)
// EPI 3: relu(acc*0.03125)^2*1024 -> fp16                          (G3)
// EPI 4: s=silu(acc+e0[col]); q=s*e1[c]+e2[c], k=s*e1[QK+c]+e2[QK+c] -> Cv,Cv2 (G2)
// EPI 5: s=silu(acc+e0[col]); col<HIDN -> v (Cv), else gate (Cv2), fp16 (G1)
template <int BT, int EPI>
__global__ void __launch_bounds__(256, 2)
gemm_h(int K, const __half* __restrict__ A, const __half* __restrict__ B,
       void* __restrict__ Cv, int ldc,
       const float* __restrict__ e0, int ld_e0, const float* __restrict__ e1,
       void* __restrict__ Cv2, const float* __restrict__ e2,
       const __half* __restrict__ eh) {
    constexpr int NST = (BT == 1) ? 3 : 2;
    constexpr int STG = (1 + BT) * 16384;
    extern __shared__ char smem_raw[];
    const uint32_t sbase = (s2u(smem_raw) + 1023u) & ~1023u;
    const int tid = threadIdx.x, lane = tid & 31, wid = tid >> 5;
    const int wm = wid & 1, wn = wid >> 1;
    const int bm = blockIdx.y * 128, bn = blockIdx.x * 128;
    const size_t ldb = (size_t)BT * K;
    const int nch = K / 64;

    auto load_chunk = [&](int c, int stg) {
        const size_t kcol = (size_t)c * 64;
        const uint32_t sA = sbase + stg * STG, sBh = sA + 16384, sBl = sA + 32768;
#pragma unroll
        for (int i = 0; i < 4; i++) {
            int idx = tid + i * 256, row = idx >> 3, seg = idx & 7;
            uint32_t b = sw((uint32_t)(row << 7) + (uint32_t)(seg << 4));
            asm volatile("cp.async.cg.shared.global [%0], [%1], 16;"
                         :: "r"(sA + b), "l"(A + (size_t)(bm + row) * K + kcol + seg * 8));
        }
#pragma unroll
        for (int i = 0; i < 4; i++) {
            int idx = tid + i * 256, row = idx >> 3, seg = idx & 7;
            uint32_t b = sw((uint32_t)(row << 7) + (uint32_t)(seg << 4));
            const __half* src = B + (size_t)(bn + row) * ldb + kcol + seg * 8;
            asm volatile("cp.async.cg.shared.global [%0], [%1], 16;" :: "r"(sBh + b), "l"(src));
            if constexpr (BT == 2)
                asm volatile("cp.async.cg.shared.global [%0], [%1], 16;" :: "r"(sBl + b), "l"(src + K));
        }
        asm volatile("cp.async.commit_group;");
    };

    float acc[4][4][4];
#pragma unroll
    for (int t = 0; t < 4; t++)
#pragma unroll
        for (int u = 0; u < 4; u++)
#pragma unroll
            for (int v = 0; v < 4; v++) acc[t][u][v] = 0.0f;

#pragma unroll
    for (int p = 0; p < NST - 1; p++) load_chunk(p, p);

    const int a_row = wm * 64 + (lane & 15);
    const int a_kx  = (lane >> 4) << 3;
    const int b_row = wn * 32 + (lane & 7) + ((lane >> 4) << 3);
    const int b_kx  = ((lane >> 3) & 1) << 3;

    int st = 0;
    for (int c = 0; c < nch; c++) {
        asm volatile("cp.async.wait_group %0;" :: "n"(NST - 2));
        __syncthreads();
        if (c + NST - 1 < nch) load_chunk(c + NST - 1, (c + NST - 1) % NST);
        else asm volatile("cp.async.commit_group;");

        const uint32_t sA = sbase + st * STG, sBh = sA + 16384, sBl = sA + 32768;
#pragma unroll
        for (int s = 0; s < 4; s++) {
            uint32_t Af[4][4], Bhf[2][4], Blf[2][4];
#pragma unroll
            for (int t = 0; t < 4; t++) {
                uint32_t rb = (uint32_t)(a_row + t * 16) << 7;
                ldm4(Af[t], sA + sw(rb + (uint32_t)((s * 16 + a_kx) << 1)));
            }
#pragma unroll
            for (int p = 0; p < 2; p++) {
                uint32_t rb = (uint32_t)(b_row + p * 16) << 7;
                int kc = s * 16 + b_kx;
                ldm4(Bhf[p], sBh + sw(rb + (uint32_t)(kc << 1)));
                if constexpr (BT == 2) ldm4(Blf[p], sBl + sw(rb + (uint32_t)(kc << 1)));
            }
#pragma unroll
            for (int t = 0; t < 4; t++)
#pragma unroll
                for (int u = 0; u < 4; u++) {
                    mma16816h(acc[t][u], Af[t], &Bhf[u >> 1][(u & 1) * 2]);
                    if constexpr (BT == 2) mma16816h(acc[t][u], Af[t], &Blf[u >> 1][(u & 1) * 2]);
                }
        }
        st = (st + 1) % NST;
    }

#pragma unroll
    for (int t = 0; t < 4; t++) {
        int row0 = bm + wm * 64 + t * 16 + (lane >> 2);
#pragma unroll
        for (int u = 0; u < 4; u++) {
            int col = bn + wn * 32 + u * 8 + (lane & 3) * 2;
#pragma unroll
            for (int h = 0; h < 2; h++) {
                int row = row0 + h * 8;
                float v0 = acc[t][u][h * 2], v1 = acc[t][u][h * 2 + 1];
                if constexpr (EPI == 0) {
                    __half2 g2 = *(const __half2*)(eh + (size_t)row * ld_e0 + col);
                    *(__half2*)((__half*)Cv + (size_t)row * ldc + col) =
                        __floats2half2_rn(v0 * 9.765625e-4f * __half2float(g2.x),
                                          v1 * 9.765625e-4f * __half2float(g2.y));
                } else if constexpr (EPI == 1) {
                    float t0 = v0 + e0[col], t1 = v1 + e0[col + 1];
                    const float* xr = e1 + (size_t)row * DIMX + col;
                    *(float2*)((float*)Cv + (size_t)row * ldc + col) =
                        make_float2(t0 * xr[0], t1 * xr[1]);
                } else if constexpr (EPI == 3) {
                    float s0 = fmaxf(v0 * 0.03125f, 0.0f), s1 = fmaxf(v1 * 0.03125f, 0.0f);
                    *(__half2*)((__half*)Cv + (size_t)row * ldc + col) =
                        __floats2half2_rn(s0 * s0 * 1024.0f, s1 * s1 * 1024.0f);
                } else if constexpr (EPI == 4) {
                    float qv[2], kv[2];
#pragma unroll
                    for (int z = 0; z < 2; z++) {
                        int cz = col + z;
                        float vz = (z == 0) ? v0 : v1;
                        if (cz < QK) {
                            float tt = vz + e0[cz];
                            float ss = tt / (1.0f + __expf(-tt));
                            qv[z] = ss * e1[cz]      + e2[cz];
                            kv[z] = ss * e1[QK + cz] + e2[QK + cz];
                        } else { qv[z] = 0.0f; kv[z] = 0.0f; }
                    }
                    *(__half2*)((__half*)Cv  + (size_t)row * ldc + col) = __floats2half2_rn(qv[0], qv[1]);
                    *(__half2*)((__half*)Cv2 + (size_t)row * ldc + col) = __floats2half2_rn(kv[0], kv[1]);
                } else {  // EPI == 5: silu -> v (col<HIDN) or gate
                    float t0 = v0 + e0[col], t1 = v1 + e0[col + 1];
                    __half2 hv = __floats2half2_rn(t0 / (1.0f + __expf(-t0)),
                                                   t1 / (1.0f + __expf(-t1)));
                    if (col < HIDN)
                        *(__half2*)((__half*)Cv  + (size_t)row * HIDN + col) = hv;
                    else
                        *(__half2*)((__half*)Cv2 + (size_t)row * HIDN + col - HIDN) = hv;
                }
            }
        }
    }
}

// fp32 -> fp16 single cast
__global__ void cast_f16(const float* __restrict__ in, __half* __restrict__ out, int total) {
    int i = blockIdx.x * blockDim.x + threadIdx.x;
    if (i < total) out[i] = __float2half(in[i]);
}

// fp32 [Kd,Nd](ld=ldi) -> fp16 [Npad, 2Kd] transposed+split
__global__ void transpose_split_f16(const float* __restrict__ in, int ldi, int Kd, int Nd,
                                    __half* __restrict__ out) {
    __shared__ float t[32][33];
    int c = blockIdx.x * 32 + threadIdx.x, r = blockIdx.y * 32 + threadIdx.y;
    t[threadIdx.y][threadIdx.x] = (c < Nd) ? in[(size_t)r * ldi + c] : 0.0f;
    __syncthreads();
    int n = blockIdx.x * 32 + threadIdx.y, k = blockIdx.y * 32 + threadIdx.x;
    __half h, l;
    hsplit(t[threadIdx.x][threadIdx.y], h, l);
    out[(size_t)n * 2 * Kd + k] = h;
    out[(size_t)n * 2 * Kd + Kd + k] = l;
}

// fp32 -> fp16 transposed [Nd, Kd]
__global__ void transpose_f16(const float* __restrict__ in, int ldi, int Kd, int Nd,
                              __half* __restrict__ out) {
    __shared__ float t[32][33];
    int c = blockIdx.x * 32 + threadIdx.x, r = blockIdx.y * 32 + threadIdx.y;
    t[threadIdx.y][threadIdx.x] = (c < Nd) ? in[(size_t)r * ldi + c] : 0.0f;
    __syncthreads();
    int n = blockIdx.x * 32 + threadIdx.y, k = blockIdx.y * 32 + threadIdx.x;
    out[(size_t)n * Kd + k] = __float2half(t[threadIdx.x][threadIdx.y]);
}

// fp16 [Kd,Nd](ld=ldi) -> fp16 transposed [Nd, Kd]
__global__ void transpose_h16(const __half* __restrict__ in, int ldi, int Kd, int Nd,
                              __half* __restrict__ out) {
    __shared__ __half t[32][40];
    int c = blockIdx.x * 32 + threadIdx.x, r = blockIdx.y * 32 + threadIdx.y;
    t[threadIdx.y][threadIdx.x] = in[(size_t)r * ldi + c];
    __syncthreads();
    int n = blockIdx.x * 32 + threadIdx.y, k = blockIdx.y * 32 + threadIdx.x;
    out[(size_t)n * Kd + k] = t[threadIdx.x][threadIdx.y];
}

static inline int cdiv(int a, int b) { return (a + b - 1) / b; }
constexpr int SMEM_H = 1024 + 2 * 3 * 16384;   // 99328

extern "C" void kernel_launch(void* const* d_in, const int* in_sizes, int n_in,
                              void* d_out, int out_size) {
    const float* x        = (const float*)d_in[0];
    const float* W_hidden = (const float*)d_in[1];
    const float* b_hidden = (const float*)d_in[2];
    const float* W_qk     = (const float*)d_in[3];
    const float* b_qk     = (const float*)d_in[4];
    const float* gamma    = (const float*)d_in[5];
    const float* beta     = (const float*)d_in[6];
    const float* W_out    = (const float*)d_in[7];
    const float* b_out    = (const float*)d_in[8];
    float* out = (float*)d_out;

    __half *xs, *WhT, *WqkT, *WoT, *v, *gate, *vT, *q, *k, *attn, *o;
    cudaGetSymbolAddress((void**)&xs, g_xs);     cudaGetSymbolAddress((void**)&WhT, g_WhT);
    cudaGetSymbolAddress((void**)&WqkT, g_WqkT); cudaGetSymbolAddress((void**)&WoT, g_WoT);
    cudaGetSymbolAddress((void**)&v, g_v);       cudaGetSymbolAddress((void**)&gate, g_gate);
    cudaGetSymbolAddress((void**)&vT, g_vT);     cudaGetSymbolAddress((void**)&q, g_q);
    cudaGetSymbolAddress((void**)&k, g_k);       cudaGetSymbolAddress((void**)&attn, g_attn);
    cudaGetSymbolAddress((void**)&o, g_o);

    cudaFuncSetAttribute((void*)gemm_h<1, 5>, cudaFuncAttributeMaxDynamicSharedMemorySize, SMEM_H);
    cudaFuncSetAttribute((void*)gemm_h<2, 4>, cudaFuncAttributeMaxDynamicSharedMemorySize, SMEM_H);
    cudaFuncSetAttribute((void*)gemm_h<1, 3>, cudaFuncAttributeMaxDynamicSharedMemorySize, SMEM_H);
    cudaFuncSetAttribute((void*)gemm_h<1, 0>, cudaFuncAttributeMaxDynamicSharedMemorySize, SMEM_H);
    cudaFuncSetAttribute((void*)gemm_h<1, 1>, cudaFuncAttributeMaxDynamicSharedMemorySize, SMEM_H);

    // Fork-join (objects leaked per call by design; only correctness+capture run host code)
    cudaStream_t s2;
    cudaStreamCreate(&s2);
    cudaEvent_t ev0, ev2;
    cudaEventCreate(&ev0); cudaEventCreate(&ev2);

    // s2: weight transposes off the critical path
    transpose_f16<<<dim3(DIMX / 32, HIDN / 32), dim3(32, 32), 0, s2>>>(W_out, DIMX, HIDN, DIMX, WoT);
    transpose_split_f16<<<dim3(QKP / 32, DIMX / 32), dim3(32, 32), 0, s2>>>(W_qk, QK, DIMX, QK, WqkT);

    // s0: x cast + Wh transpose
    cast_f16<<<cdiv(NROWS * DIMX, 256), 256>>>(x, xs, NROWS * DIMX);
    transpose_f16<<<dim3(H2 / 32, DIMX / 32), dim3(32, 32)>>>(W_hidden, H2, DIMX, H2, WhT);
    cudaEventRecord(ev0, 0);
    cudaStreamWaitEvent(s2, ev0, 0);

    // s2: G2 (q,k fused) -> G3 (attn)
    gemm_h<2, 4><<<dim3(QKP / 128, NROWS / 128), 256, SMEM_H, s2>>>(
        DIMX, xs, WqkT, q, QKP, b_qk, 0, gamma, k, beta, nullptr);
    gemm_h<1, 3><<<dim3(NROWS / 128, NROWS / 128), 256, SMEM_H, s2>>>(
        QKP, q, k, attn, NROWS, nullptr, 0, nullptr, nullptr, nullptr, nullptr);
    cudaEventRecord(ev2, s2);

    // s0: G1 -> v/gate fp16 directly, then vT
    gemm_h<1, 5><<<dim3(H2 / 128, NROWS / 128), 256, SMEM_H>>>(
        DIMX, xs, WhT, v, HIDN, b_hidden, 0, nullptr, gate, nullptr, nullptr);
    transpose_h16<<<dim3(HIDN / 32, NROWS / 32), dim3(32, 32)>>>(v, HIDN, NROWS, HIDN, vT);

    // join attn; monolithic G4 then G5 on stream 0
    cudaStreamWaitEvent(0, ev2, 0);
    gemm_h<1, 0><<<dim3(HIDN / 128, NROWS / 128), 256, SMEM_H>>>(
        NROWS, attn, vT, o, HIDN, nullptr, HIDN, nullptr, nullptr, nullptr, gate);
    gemm_h<1, 1><<<dim3(DIMX / 128, NROWS / 128), 256, SMEM_H>>>(
        HIDN, o, WoT, out, DIMX, b_out, 0, x, nullptr, nullptr, nullptr);
}

// round 16
// speedup vs baseline: 1.1648x; 1.0465x over previous
#include <cuda_runtime.h>
#include <cuda_fp16.h>
#include <cstdint>
#include <cstddef>

#define NROWS 8192
#define DIMX  1024
#define HIDN  2048
#define H2    4096
#define QK    200
#define QKP   256

// scratch
__device__ __half g_xs  [(size_t)NROWS * DIMX];
__device__ __half g_WhT [(size_t)H2    * DIMX];
__device__ __half g_WqkT[(size_t)QKP   * 2 * DIMX];
__device__ __half g_WoT [(size_t)DIMX  * HIDN];
__device__ __half g_v   [(size_t)NROWS * HIDN];
__device__ __half g_gate[(size_t)NROWS * HIDN];
__device__ __half g_vT  [(size_t)HIDN  * NROWS];
__device__ __half g_q   [(size_t)NROWS * QKP];
__device__ __half g_k   [(size_t)NROWS * QKP];
__device__ __half g_attn[(size_t)NROWS * NROWS];
__device__ __half g_o   [(size_t)NROWS * HIDN];
__device__ int    g_cnt [NROWS / 128];               // row-block completion counters

__device__ __forceinline__ uint32_t s2u(const void* p) {
    uint32_t r;
    asm("{ .reg .u64 t; cvta.to.shared.u64 t, %1; cvt.u32.u64 %0, t; }" : "=r"(r) : "l"(p));
    return r;
}
__device__ __forceinline__ uint32_t sw(uint32_t b) { return b ^ ((b >> 3) & 0x70); }
__device__ __forceinline__ void ldm4(uint32_t* r, uint32_t addr) {
    asm volatile("ldmatrix.sync.aligned.m8n8.x4.shared.b16 {%0,%1,%2,%3}, [%4];"
                 : "=r"(r[0]), "=r"(r[1]), "=r"(r[2]), "=r"(r[3]) : "r"(addr));
}
__device__ __forceinline__ void mma16816h(float* c, const uint32_t* a, const uint32_t* b) {
    asm volatile("mma.sync.aligned.m16n8k16.row.col.f32.f16.f16.f32 "
                 "{%0,%1,%2,%3}, {%4,%5,%6,%7}, {%8,%9}, {%0,%1,%2,%3};"
                 : "+f"(c[0]), "+f"(c[1]), "+f"(c[2]), "+f"(c[3])
                 : "r"(a[0]), "r"(a[1]), "r"(a[2]), "r"(a[3]), "r"(b[0]), "r"(b[1]));
}
__device__ __forceinline__ void hsplit(float v, __half& h, __half& l) {
    h = __float2half(v);
    l = __float2half(v - __half2float(h));
}

constexpr int SMEM_H = 1024 + 2 * 3 * 16384;   // 99328

// ---------------- BT=1 GEMM body (tile 128x128, warp 64x32, 3-stage) --------
// EPI 0: acc*(1/1024)*eh[row*ld+col] -> fp16   | EPI 1: (acc+e0[col])*e1[row*DIMX+col] -> f32
template <int EPI>
__device__ __forceinline__ void gemm_body(
    int K, const __half* __restrict__ A, const __half* __restrict__ B,
    void* __restrict__ Cv, int ldc,
    const float* __restrict__ e0, const float* __restrict__ e1,
    const __half* __restrict__ eh, int ld_eh,
    int bm, int bn, uint32_t sbase) {
    constexpr int STG = 2 * 16384;
    const int tid = threadIdx.x, lane = tid & 31, wid = tid >> 5;
    const int wm = wid & 1, wn = wid >> 1;
    const int nch = K / 64;

    auto load_chunk = [&](int c, int stg) {
        const size_t kcol = (size_t)c * 64;
        const uint32_t sA = sbase + stg * STG, sB = sA + 16384;
#pragma unroll
        for (int i = 0; i < 4; i++) {
            int idx = tid + i * 256, row = idx >> 3, seg = idx & 7;
            uint32_t b = sw((uint32_t)(row << 7) + (uint32_t)(seg << 4));
            asm volatile("cp.async.cg.shared.global [%0], [%1], 16;"
                         :: "r"(sA + b), "l"(A + (size_t)(bm + row) * K + kcol + seg * 8));
        }
#pragma unroll
        for (int i = 0; i < 4; i++) {
            int idx = tid + i * 256, row = idx >> 3, seg = idx & 7;
            uint32_t b = sw((uint32_t)(row << 7) + (uint32_t)(seg << 4));
            asm volatile("cp.async.cg.shared.global [%0], [%1], 16;"
                         :: "r"(sB + b), "l"(B + (size_t)(bn + row) * K + kcol + seg * 8));
        }
        asm volatile("cp.async.commit_group;");
    };

    float acc[4][4][4];
#pragma unroll
    for (int t = 0; t < 4; t++)
#pragma unroll
        for (int u = 0; u < 4; u++)
#pragma unroll
            for (int v = 0; v < 4; v++) acc[t][u][v] = 0.0f;

    load_chunk(0, 0); load_chunk(1, 1);

    const int a_row = wm * 64 + (lane & 15);
    const int a_kx  = (lane >> 4) << 3;
    const int b_row = wn * 32 + (lane & 7) + ((lane >> 4) << 3);
    const int b_kx  = ((lane >> 3) & 1) << 3;

    int st = 0;
    for (int c = 0; c < nch; c++) {
        asm volatile("cp.async.wait_group 1;");
        __syncthreads();
        if (c + 2 < nch) load_chunk(c + 2, (c + 2) % 3);
        else asm volatile("cp.async.commit_group;");

        const uint32_t sA = sbase + st * STG, sB = sA + 16384;
#pragma unroll
        for (int s = 0; s < 4; s++) {
            uint32_t Af[4][4], Bf[2][4];
#pragma unroll
            for (int t = 0; t < 4; t++) {
                uint32_t rb = (uint32_t)(a_row + t * 16) << 7;
                ldm4(Af[t], sA + sw(rb + (uint32_t)((s * 16 + a_kx) << 1)));
            }
#pragma unroll
            for (int p = 0; p < 2; p++) {
                uint32_t rb = (uint32_t)(b_row + p * 16) << 7;
                ldm4(Bf[p], sB + sw(rb + (uint32_t)((s * 16 + b_kx) << 1)));
            }
#pragma unroll
            for (int t = 0; t < 4; t++)
#pragma unroll
                for (int u = 0; u < 4; u++)
                    mma16816h(acc[t][u], Af[t], &Bf[u >> 1][(u & 1) * 2]);
        }
        st = (st + 1) % 3;
    }

#pragma unroll
    for (int t = 0; t < 4; t++) {
        int row0 = bm + wm * 64 + t * 16 + (lane >> 2);
#pragma unroll
        for (int u = 0; u < 4; u++) {
            int col = bn + wn * 32 + u * 8 + (lane & 3) * 2;
#pragma unroll
            for (int h = 0; h < 2; h++) {
                int row = row0 + h * 8;
                float v0 = acc[t][u][h * 2], v1 = acc[t][u][h * 2 + 1];
                if constexpr (EPI == 0) {
                    __half2 g2 = *(const __half2*)(eh + (size_t)row * ld_eh + col);
                    *(__half2*)((__half*)Cv + (size_t)row * ldc + col) =
                        __floats2half2_rn(v0 * 9.765625e-4f * __half2float(g2.x),
                                          v1 * 9.765625e-4f * __half2float(g2.y));
                } else {
                    float t0 = v0 + e0[col], t1 = v1 + e0[col + 1];
                    const float* xr = e1 + (size_t)row * DIMX + col;
                    *(float2*)((float*)Cv + (size_t)row * ldc + col) =
                        make_float2(t0 * xr[0], t1 * xr[1]);
                }
            }
        }
    }
}

// ---------------- fused G4+G5 kernel: bids 0..1023 = G4 tiles, 1024.. = G5 ---
__global__ void __launch_bounds__(256, 2)
g45(const __half* __restrict__ attn, const __half* __restrict__ vT,
    __half* __restrict__ o, const __half* __restrict__ gate,
    const __half* __restrict__ WoT, float* __restrict__ out,
    const float* __restrict__ b_out, const float* __restrict__ x,
    int* __restrict__ cnt) {
    extern __shared__ char smem_raw[];
    const uint32_t sbase = (s2u(smem_raw) + 1023u) & ~1023u;
    const int bid = blockIdx.x;
    if (bid < 1024) {
        const int m = bid >> 4, n = bid & 15;
        gemm_body<0>(NROWS, attn, vT, o, HIDN, nullptr, nullptr, gate, HIDN,
                     m * 128, n * 128, sbase);
        __threadfence();
        __syncthreads();
        if (threadIdx.x == 0) atomicAdd(&cnt[m], 1);
    } else {
        const int idx = bid - 1024, m = idx >> 3, n = idx & 7;
        if (threadIdx.x == 0) {
            while (atomicAdd(&cnt[m], 0) < 16) __nanosleep(128);
        }
        __syncthreads();
        __threadfence();
        gemm_body<1>(HIDN, o, WoT, out, DIMX, b_out, x, nullptr, 0,
                     m * 128, n * 128, sbase);
    }
}

__global__ void zero_cnt(int* __restrict__ cnt) { cnt[threadIdx.x] = 0; }

// ---------------- general GEMM for G1/G2/G3 (as in R15) ---------------------
// EPI 3: relu(acc*0.03125)^2*1024 -> fp16 | EPI 4: fused qk affine -> Cv,Cv2
// EPI 5: silu -> v (col<HIDN) or gate
template <int BT, int EPI>
__global__ void __launch_bounds__(256, 2)
gemm_h(int K, const __half* __restrict__ A, const __half* __restrict__ B,
       void* __restrict__ Cv, int ldc,
       const float* __restrict__ e0, const float* __restrict__ e1,
       void* __restrict__ Cv2, const float* __restrict__ e2) {
    constexpr int NST = (BT == 1) ? 3 : 2;
    constexpr int STG = (1 + BT) * 16384;
    extern __shared__ char smem_raw[];
    const uint32_t sbase = (s2u(smem_raw) + 1023u) & ~1023u;
    const int tid = threadIdx.x, lane = tid & 31, wid = tid >> 5;
    const int wm = wid & 1, wn = wid >> 1;
    const int bm = blockIdx.y * 128, bn = blockIdx.x * 128;
    const size_t ldb = (size_t)BT * K;
    const int nch = K / 64;

    auto load_chunk = [&](int c, int stg) {
        const size_t kcol = (size_t)c * 64;
        const uint32_t sA = sbase + stg * STG, sBh = sA + 16384, sBl = sA + 32768;
#pragma unroll
        for (int i = 0; i < 4; i++) {
            int idx = tid + i * 256, row = idx >> 3, seg = idx & 7;
            uint32_t b = sw((uint32_t)(row << 7) + (uint32_t)(seg << 4));
            asm volatile("cp.async.cg.shared.global [%0], [%1], 16;"
                         :: "r"(sA + b), "l"(A + (size_t)(bm + row) * K + kcol + seg * 8));
        }
#pragma unroll
        for (int i = 0; i < 4; i++) {
            int idx = tid + i * 256, row = idx >> 3, seg = idx & 7;
            uint32_t b = sw((uint32_t)(row << 7) + (uint32_t)(seg << 4));
            const __half* src = B + (size_t)(bn + row) * ldb + kcol + seg * 8;
            asm volatile("cp.async.cg.shared.global [%0], [%1], 16;" :: "r"(sBh + b), "l"(src));
            if constexpr (BT == 2)
                asm volatile("cp.async.cg.shared.global [%0], [%1], 16;" :: "r"(sBl + b), "l"(src + K));
        }
        asm volatile("cp.async.commit_group;");
    };

    float acc[4][4][4];
#pragma unroll
    for (int t = 0; t < 4; t++)
#pragma unroll
        for (int u = 0; u < 4; u++)
#pragma unroll
            for (int v = 0; v < 4; v++) acc[t][u][v] = 0.0f;

#pragma unroll
    for (int p = 0; p < NST - 1; p++) load_chunk(p, p);

    const int a_row = wm * 64 + (lane & 15);
    const int a_kx  = (lane >> 4) << 3;
    const int b_row = wn * 32 + (lane & 7) + ((lane >> 4) << 3);
    const int b_kx  = ((lane >> 3) & 1) << 3;

    int st = 0;
    for (int c = 0; c < nch; c++) {
        asm volatile("cp.async.wait_group %0;" :: "n"(NST - 2));
        __syncthreads();
        if (c + NST - 1 < nch) load_chunk(c + NST - 1, (c + NST - 1) % NST);
        else asm volatile("cp.async.commit_group;");

        const uint32_t sA = sbase + st * STG, sBh = sA + 16384, sBl = sA + 32768;
#pragma unroll
        for (int s = 0; s < 4; s++) {
            uint32_t Af[4][4], Bhf[2][4], Blf[2][4];
#pragma unroll
            for (int t = 0; t < 4; t++) {
                uint32_t rb = (uint32_t)(a_row + t * 16) << 7;
                ldm4(Af[t], sA + sw(rb + (uint32_t)((s * 16 + a_kx) << 1)));
            }
#pragma unroll
            for (int p = 0; p < 2; p++) {
                uint32_t rb = (uint32_t)(b_row + p * 16) << 7;
                int kc = s * 16 + b_kx;
                ldm4(Bhf[p], sBh + sw(rb + (uint32_t)(kc << 1)));
                if constexpr (BT == 2) ldm4(Blf[p], sBl + sw(rb + (uint32_t)(kc << 1)));
            }
#pragma unroll
            for (int t = 0; t < 4; t++)
#pragma unroll
                for (int u = 0; u < 4; u++) {
                    mma16816h(acc[t][u], Af[t], &Bhf[u >> 1][(u & 1) * 2]);
                    if constexpr (BT == 2) mma16816h(acc[t][u], Af[t], &Blf[u >> 1][(u & 1) * 2]);
                }
        }
        st = (st + 1) % NST;
    }

#pragma unroll
    for (int t = 0; t < 4; t++) {
        int row0 = bm + wm * 64 + t * 16 + (lane >> 2);
#pragma unroll
        for (int u = 0; u < 4; u++) {
            int col = bn + wn * 32 + u * 8 + (lane & 3) * 2;
#pragma unroll
            for (int h = 0; h < 2; h++) {
                int row = row0 + h * 8;
                float v0 = acc[t][u][h * 2], v1 = acc[t][u][h * 2 + 1];
                if constexpr (EPI == 3) {
                    float s0 = fmaxf(v0 * 0.03125f, 0.0f), s1 = fmaxf(v1 * 0.03125f, 0.0f);
                    *(__half2*)((__half*)Cv + (size_t)row * ldc + col) =
                        __floats2half2_rn(s0 * s0 * 1024.0f, s1 * s1 * 1024.0f);
                } else if constexpr (EPI == 4) {
                    float qv[2], kv[2];
#pragma unroll
                    for (int z = 0; z < 2; z++) {
                        int cz = col + z;
                        float vz = (z == 0) ? v0 : v1;
                        if (cz < QK) {
                            float tt = vz + e0[cz];
                            float ss = tt / (1.0f + __expf(-tt));
                            qv[z] = ss * e1[cz]      + e2[cz];
                            kv[z] = ss * e1[QK + cz] + e2[QK + cz];
                        } else { qv[z] = 0.0f; kv[z] = 0.0f; }
                    }
                    *(__half2*)((__half*)Cv  + (size_t)row * ldc + col) = __floats2half2_rn(qv[0], qv[1]);
                    *(__half2*)((__half*)Cv2 + (size_t)row * ldc + col) = __floats2half2_rn(kv[0], kv[1]);
                } else {  // EPI == 5
                    float t0 = v0 + e0[col], t1 = v1 + e0[col + 1];
                    __half2 hv = __floats2half2_rn(t0 / (1.0f + __expf(-t0)),
                                                   t1 / (1.0f + __expf(-t1)));
                    if (col < HIDN)
                        *(__half2*)((__half*)Cv  + (size_t)row * HIDN + col) = hv;
                    else
                        *(__half2*)((__half*)Cv2 + (size_t)row * HIDN + col - HIDN) = hv;
                }
            }
        }
    }
}

// ---------------- conversions ------------------------------------------------
__global__ void cast_f16(const float* __restrict__ in, __half* __restrict__ out, int total) {
    int i = blockIdx.x * blockDim.x + threadIdx.x;
    if (i < total) out[i] = __float2half(in[i]);
}
__global__ void transpose_split_f16(const float* __restrict__ in, int ldi, int Kd, int Nd,
                                    __half* __restrict__ out) {
    __shared__ float t[32][33];
    int c = blockIdx.x * 32 + threadIdx.x, r = blockIdx.y * 32 + threadIdx.y;
    t[threadIdx.y][threadIdx.x] = (c < Nd) ? in[(size_t)r * ldi + c] : 0.0f;
    __syncthreads();
    int n = blockIdx.x * 32 + threadIdx.y, k = blockIdx.y * 32 + threadIdx.x;
    __half h, l;
    hsplit(t[threadIdx.x][threadIdx.y], h, l);
    out[(size_t)n * 2 * Kd + k] = h;
    out[(size_t)n * 2 * Kd + Kd + k] = l;
}
__global__ void transpose_f16(const float* __restrict__ in, int ldi, int Kd, int Nd,
                              __half* __restrict__ out) {
    __shared__ float t[32][33];
    int c = blockIdx.x * 32 + threadIdx.x, r = blockIdx.y * 32 + threadIdx.y;
    t[threadIdx.y][threadIdx.x] = (c < Nd) ? in[(size_t)r * ldi + c] : 0.0f;
    __syncthreads();
    int n = blockIdx.x * 32 + threadIdx.y, k = blockIdx.y * 32 + threadIdx.x;
    out[(size_t)n * Kd + k] = __float2half(t[threadIdx.x][threadIdx.y]);
}
__global__ void transpose_h16(const __half* __restrict__ in, int ldi, int Kd, int Nd,
                              __half* __restrict__ out) {
    __shared__ __half t[32][40];
    int c = blockIdx.x * 32 + threadIdx.x, r = blockIdx.y * 32 + threadIdx.y;
    t[threadIdx.y][threadIdx.x] = in[(size_t)r * ldi + c];
    __syncthreads();
    int n = blockIdx.x * 32 + threadIdx.y, k = blockIdx.y * 32 + threadIdx.x;
    out[(size_t)n * Kd + k] = t[threadIdx.x][threadIdx.y];
}

static inline int cdiv(int a, int b) { return (a + b - 1) / b; }

extern "C" void kernel_launch(void* const* d_in, const int* in_sizes, int n_in,
                              void* d_out, int out_size) {
    const float* x        = (const float*)d_in[0];
    const float* W_hidden = (const float*)d_in[1];
    const float* b_hidden = (const float*)d_in[2];
    const float* W_qk     = (const float*)d_in[3];
    const float* b_qk     = (const float*)d_in[4];
    const float* gamma    = (const float*)d_in[5];
    const float* beta     = (const float*)d_in[6];
    const float* W_out    = (const float*)d_in[7];
    const float* b_out    = (const float*)d_in[8];
    float* out = (float*)d_out;

    __half *xs, *WhT, *WqkT, *WoT, *v, *gate, *vT, *q, *k, *attn, *o;
    int* cnt;
    cudaGetSymbolAddress((void**)&xs, g_xs);     cudaGetSymbolAddress((void**)&WhT, g_WhT);
    cudaGetSymbolAddress((void**)&WqkT, g_WqkT); cudaGetSymbolAddress((void**)&WoT, g_WoT);
    cudaGetSymbolAddress((void**)&v, g_v);       cudaGetSymbolAddress((void**)&gate, g_gate);
    cudaGetSymbolAddress((void**)&vT, g_vT);     cudaGetSymbolAddress((void**)&q, g_q);
    cudaGetSymbolAddress((void**)&k, g_k);       cudaGetSymbolAddress((void**)&attn, g_attn);
    cudaGetSymbolAddress((void**)&o, g_o);       cudaGetSymbolAddress((void**)&cnt, g_cnt);

    cudaFuncSetAttribute((void*)gemm_h<1, 5>, cudaFuncAttributeMaxDynamicSharedMemorySize, SMEM_H);
    cudaFuncSetAttribute((void*)gemm_h<2, 4>, cudaFuncAttributeMaxDynamicSharedMemorySize, SMEM_H);
    cudaFuncSetAttribute((void*)gemm_h<1, 3>, cudaFuncAttributeMaxDynamicSharedMemorySize, SMEM_H);
    cudaFuncSetAttribute((void*)g45,          cudaFuncAttributeMaxDynamicSharedMemorySize, SMEM_H);

    // Fork-join (objects leaked per call by design; only correctness+capture run host code)
    cudaStream_t s2;
    cudaStreamCreate(&s2);
    cudaEvent_t ev0, ev2;
    cudaEventCreate(&ev0); cudaEventCreate(&ev2);

    // s2: weight transposes off the critical path
    transpose_f16<<<dim3(DIMX / 32, HIDN / 32), dim3(32, 32), 0, s2>>>(W_out, DIMX, HIDN, DIMX, WoT);
    transpose_split_f16<<<dim3(QKP / 32, DIMX / 32), dim3(32, 32), 0, s2>>>(W_qk, QK, DIMX, QK, WqkT);

    // s0: counter zero + x cast + Wh transpose
    zero_cnt<<<1, NROWS / 128>>>(cnt);
    cast_f16<<<cdiv(NROWS * DIMX, 256), 256>>>(x, xs, NROWS * DIMX);
    transpose_f16<<<dim3(H2 / 32, DIMX / 32), dim3(32, 32)>>>(W_hidden, H2, DIMX, H2, WhT);
    cudaEventRecord(ev0, 0);
    cudaStreamWaitEvent(s2, ev0, 0);

    // s2: G2 (q,k fused) -> G3 (attn)
    gemm_h<2, 4><<<dim3(QKP / 128, NROWS / 128), 256, SMEM_H, s2>>>(
        DIMX, xs, WqkT, q, QKP, b_qk, gamma, k, beta);
    gemm_h<1, 3><<<dim3(NROWS / 128, NROWS / 128), 256, SMEM_H, s2>>>(
        QKP, q, k, attn, NROWS, nullptr, nullptr, nullptr, nullptr);
    cudaEventRecord(ev2, s2);

    // s0: G1 -> v/gate fp16 directly, then vT
    gemm_h<1, 5><<<dim3(H2 / 128, NROWS / 128), 256, SMEM_H>>>(
        DIMX, xs, WhT, v, HIDN, b_hidden, nullptr, gate, nullptr);
    transpose_h16<<<dim3(HIDN / 32, NROWS / 32), dim3(32, 32)>>>(v, HIDN, NROWS, HIDN, vT);

    // join attn; fused G4+G5 single launch (1024 G4 tiles + 512 G5 tiles)
    cudaStreamWaitEvent(0, ev2, 0);
    g45<<<1536, 256, SMEM_H>>>(attn, vT, o, gate, WoT, out, b_out, x, cnt);
}